// round 14
// baseline (speedup 1.0000x reference)
#include <cuda_runtime.h>
#include <cuda_fp16.h>
#include <math.h>
#include <stdint.h>

// Problem constants
#define BB 32
#define NN 4096
#define DD 512
#define CC 64
#define RTOT (BB*NN)          // 131072 rows
#define MT 32                 // rows per GEMM tile
#define NTILES (RTOT/MT)      // 4096
#define PB 528                // int8 row pitch in bytes (132 words ≡ 4 mod 32)
#define DP 65                 // dots pitch in ints
#define CHUNK 128             // rows per feature chunk
#define NCHUNK (NN/CHUNK)     // 32

// Device scratch (allocation-free rule: __device__ globals)
__device__ float  g_sw[(size_t)RTOT*CC];          // score*invnorm*valid, 32 MiB
__device__ __half g_xh[(size_t)RTOT*DD];          // x in fp16 (written by main), 128 MiB
__device__ int    g_counts[BB*CC];
__device__ int    g_index[BB];
__device__ float  g_part[(size_t)BB*NCHUNK*DD];   // 2 MiB

// mask may be int64 (jax x64) or int32. Values in [1,4096]: if int64 LE,
// word 1 (high half of elem 0) is 0.
__device__ __forceinline__ int decode_mask(const int* mr, int b) {
    return (mr[1] == 0) ? mr[2*b] : mr[b];
}

__device__ __forceinline__ unsigned pack4(float a, float b, float c, float d, float r) {
    int q0 = __float2int_rn(a*r), q1 = __float2int_rn(b*r);
    int q2 = __float2int_rn(c*r), q3 = __float2int_rn(d*r);
    return (unsigned)(q0 & 0xff) | ((unsigned)(q1 & 0xff) << 8)
         | ((unsigned)(q2 & 0xff) << 16) | ((unsigned)(q3 & 0xff) << 24);
}

// s8 mma: D(s32) = A(s8,16x32) * B(s8,32x8) + C(s32)
__device__ __forceinline__ void mma_s8(int* d,
                                       unsigned a0, unsigned a1, unsigned a2, unsigned a3,
                                       unsigned b0, unsigned b1) {
    asm volatile("mma.sync.aligned.m16n8k32.row.col.s32.s8.s8.s32 "
                 "{%0,%1,%2,%3}, {%4,%5,%6,%7}, {%8,%9}, {%0,%1,%2,%3};"
                 : "+r"(d[0]), "+r"(d[1]), "+r"(d[2]), "+r"(d[3])
                 : "r"(a0), "r"(a1), "r"(a2), "r"(a3), "r"(b0), "r"(b1));
}

__global__ __launch_bounds__(512, 1)
void main_kernel(const float* __restrict__ x, const int* __restrict__ maskr,
                 const float* __restrict__ anchors) {
    extern __shared__ __align__(16) char smem[];
    char*  a_s8     = smem;                         // [CC][PB] anchors int8
    char*  x_s8     = smem + CC*PB;                 // [MT][PB] x tile int8
    int*   dots_i   = (int*)(smem + CC*PB + MT*PB); // [2][MT][DP] s32 k-half partials
    float* anorm_s  = (float*)(dots_i + 2*MT*DP);   // [CC]
    float* ascale_s = anorm_s + CC;                 // [CC]  Sa = max(a_c)/127
    float* norm_s   = ascale_s + CC;                // [MT]
    float* xs_s     = norm_s + MT;                  // [MT]  max|x_row|/127
    int*   mask_s   = (int*)(xs_s + MT);            // [BB]

    const int tid  = threadIdx.x;
    const int lane = tid & 31, warp = tid >> 5;     // 16 warps

    // ---- anchor norms + scales ----
    if (tid < BB) mask_s[tid] = decode_mask(maskr, tid);
    if (tid < CC) {
        float s = 0.f, mx = 0.f;
        const float* ar = anchors + (size_t)tid*DD;
        #pragma unroll 8
        for (int k = 0; k < DD; k++) {
            float q = ar[k];
            s = fmaf(q, q, s);
            mx = fmaxf(mx, fabsf(q));
        }
        anorm_s[tid] = s;
        ascale_s[tid] = fmaxf(mx, 1e-20f) * (1.f/127.f);
    }
    __syncthreads();

    // ---- quantize anchors -> int8 smem ----
    for (int i4 = tid; i4 < CC*128; i4 += 512) {
        int c = i4 >> 7, k4 = i4 & 127;
        float4 q = ((const float4*)anchors)[i4];
        float r = 1.f / ascale_s[c];
        *(unsigned*)(a_s8 + c*PB + k4*4) = pack4(q.x, q.y, q.z, q.w, r);
    }
    __syncthreads();

    // warp decomposition: mslice (2) x nslice (4) x khalf (2)
    const int gid = lane >> 2, tig = lane & 3;
    const int mbase = (warp & 1) * 16;
    const int nb0   = ((warp >> 1) & 3) * 16;
    const int kh    = warp >> 3;                 // 0/1: k byte offset kh*256

    // load mapping: thread -> one row, 8 float4 slots
    const int lrow  = tid >> 4;                  // 0..31
    const int lslot = tid & 15;

    // ---- find first valid tile, prefetch into registers ----
    int tile = blockIdx.x;
    while (tile < NTILES) {
        int bb = (tile*MT) >> 12;
        if (((tile*MT) & (NN-1)) < mask_s[bb]) break;
        tile += gridDim.x;
    }
    float4 v[8];
    if (tile < NTILES) {
        const float4* xg = (const float4*)(x + (size_t)tile*MT*DD) + lrow*128 + lslot;
        #pragma unroll
        for (int j = 0; j < 8; j++) v[j] = xg[16*j];
    }

    while (tile < NTILES) {
        const int rowbase = tile*MT;
        const int b = rowbase >> 12;

        // ---- norm + maxabs reduce, then quantize tile -> int8 smem + fp16 mirror ----
        float ns = 0.f, mxa = 0.f;
        #pragma unroll
        for (int j = 0; j < 8; j++) {
            float4 q = v[j];
            ns = fmaf(q.x,q.x, fmaf(q.y,q.y, fmaf(q.z,q.z, fmaf(q.w,q.w, ns))));
            mxa = fmaxf(mxa, fmaxf(fmaxf(fabsf(q.x), fabsf(q.y)),
                                   fmaxf(fabsf(q.z), fabsf(q.w))));
        }
        #pragma unroll
        for (int o = 8; o; o >>= 1) {
            ns  += __shfl_xor_sync(0xffffffffu, ns, o);
            mxa  = fmaxf(mxa, __shfl_xor_sync(0xffffffffu, mxa, o));
        }
        mxa = fmaxf(mxa, 1e-20f);
        if ((lane & 15) == 0) {
            norm_s[lrow] = ns;
            xs_s[lrow]   = mxa * (1.f/127.f);
        }
        {
            const float r127 = 127.f / mxa;
            char* xrow = x_s8 + lrow*PB;
            uint2* xhrow = (uint2*)(g_xh + (size_t)(rowbase + lrow)*DD);
            #pragma unroll
            for (int j = 0; j < 8; j++) {
                float4 q = v[j];
                int slot = lslot + 16*j;
                *(unsigned*)(xrow + slot*4) = pack4(q.x, q.y, q.z, q.w, r127);
                __half2 h01 = __floats2half2_rn(q.x, q.y);
                __half2 h23 = __floats2half2_rn(q.z, q.w);
                uint2 st;
                st.x = *(unsigned*)&h01;
                st.y = *(unsigned*)&h23;
                xhrow[slot] = st;
            }
        }
        __syncthreads();

        // ---- find + prefetch next valid tile (overlaps with mma) ----
        int nt = tile + gridDim.x;
        while (nt < NTILES) {
            int nb = (nt*MT) >> 12;
            if (((nt*MT) & (NN-1)) < mask_s[nb]) break;
            nt += gridDim.x;
        }
        if (nt < NTILES) {
            const float4* xg = (const float4*)(x + (size_t)nt*MT*DD) + lrow*128 + lslot;
            #pragma unroll
            for (int j = 0; j < 8; j++) v[j] = xg[16*j];
        }

        // ---- s8 mma: warp = 16 rows x 16 cols over its 256-k half (8 k32 steps) ----
        {
            int acc0[4] = {0,0,0,0}, acc1[4] = {0,0,0,0};
            const char* xa = x_s8 + (mbase + gid)*PB + kh*256 + 4*tig;
            const char* bA = a_s8 + (nb0 + gid)*PB   + kh*256 + 4*tig;
            const char* bB = bA + 8*PB;
            #pragma unroll
            for (int ks = 0; ks < 8; ks++) {
                const int k0 = ks*32;
                unsigned a0 = *(const unsigned*)(xa + k0);
                unsigned a1 = *(const unsigned*)(xa + 8*PB + k0);
                unsigned a2 = *(const unsigned*)(xa + k0 + 16);
                unsigned a3 = *(const unsigned*)(xa + 8*PB + k0 + 16);
                unsigned b0 = *(const unsigned*)(bA + k0);
                unsigned b1 = *(const unsigned*)(bA + k0 + 16);
                unsigned b2 = *(const unsigned*)(bB + k0);
                unsigned b3 = *(const unsigned*)(bB + k0 + 16);
                mma_s8(acc0, a0,a1,a2,a3, b0,b1);
                mma_s8(acc1, a0,a1,a2,a3, b2,b3);
            }
            int* dh = dots_i + kh*MT*DP;
            const int r0 = mbase + gid, r1 = r0 + 8, cb = 2*tig;
            dh[r0*DP + nb0 + cb]         = acc0[0];
            dh[r0*DP + nb0 + cb + 1]     = acc0[1];
            dh[r1*DP + nb0 + cb]         = acc0[2];
            dh[r1*DP + nb0 + cb + 1]     = acc0[3];
            dh[r0*DP + nb0 + 8 + cb]     = acc1[0];
            dh[r0*DP + nb0 + 8 + cb + 1] = acc1[1];
            dh[r1*DP + nb0 + 8 + cb]     = acc1[2];
            dh[r1*DP + nb0 + 8 + cb + 1] = acc1[3];
        }
        __syncthreads();

        // ---- epilogue: 2 rows per warp; softmax without max-shift ----
        // (invd <= ~0.09 always since ||anchor|| >= ~12, ||xn|| = 1 -> no overflow)
        #pragma unroll
        for (int u = 0; u < 2; u++) {
            const int m = warp*2 + u;
            const int row = rowbase + m;
            const int n = row & (NN-1);
            const bool valid = n < mask_s[b];
            const float n2  = norm_s[m];
            const float inv = 1.f / fmaxf(sqrtf(n2), 1e-12f);
            const float fx  = inv * xs_s[m];           // per-row dequant incl. 1/||x||
            const float sxn2 = n2 * inv * inv;
            const int cA = lane, cB = lane + 32;
            const int iA = dots_i[m*DP + cA] + dots_i[MT*DP + m*DP + cA];
            const int iB = dots_i[m*DP + cB] + dots_i[MT*DP + m*DP + cB];
            const float dnA = fx * ascale_s[cA] * (float)iA;
            const float dnB = fx * ascale_s[cB] * (float)iB;
            const float sqA = sxn2 + anorm_s[cA] - 2.f*dnA;
            const float sqB = sxn2 + anorm_s[cB] - 2.f*dnB;
            const float idA = rsqrtf(fmaxf(sqA, 1e-30f));
            const float idB = rsqrtf(fmaxf(sqB, 1e-30f));
            const float eA = __expf(idA), eB = __expf(idB);
            float ss = eA + eB;
            #pragma unroll
            for (int o = 16; o; o >>= 1) ss += __shfl_xor_sync(0xffffffffu, ss, o);
            const float rs = 1.f / ss;
            const size_t base = (size_t)row * CC;
            g_sw[base + cA] = valid ? eA*rs*inv : 0.f;
            g_sw[base + cB] = valid ? eB*rs*inv : 0.f;
            float bv; int bi;
            if (idB > idA) { bv = idB; bi = cB; } else { bv = idA; bi = cA; }
            #pragma unroll
            for (int o = 16; o; o >>= 1) {
                float ov = __shfl_xor_sync(0xffffffffu, bv, o);
                int   oi = __shfl_xor_sync(0xffffffffu, bi, o);
                if (ov > bv || (ov == bv && oi < bi)) { bv = ov; bi = oi; }
            }
            if (lane == 0 && valid) atomicAdd(&g_counts[b*CC + bi], 1);
        }
        __syncthreads();
        tile = nt;
    }
}

// argmax of counts per batch; also resets counts for the next graph replay
__global__ void index_kernel() {
    __shared__ int sv[CC], si[CC];
    const int b = blockIdx.x, c = threadIdx.x;
    sv[c] = g_counts[b*CC + c]; si[c] = c;
    g_counts[b*CC + c] = 0;
    __syncthreads();
    for (int o = 32; o; o >>= 1) {
        if (c < o) {
            if (sv[c+o] > sv[c] || (sv[c+o] == sv[c] && si[c+o] < si[c])) {
                sv[c] = sv[c+o]; si[c] = si[c+o];
            }
        }
        __syncthreads();
    }
    if (c == 0) g_index[b] = si[0];
}

// reads fp16 x copy (half traffic); thread tid covers d = {2*tid, 2*tid+1}
__global__ __launch_bounds__(256)
void feat_part_kernel(const int* __restrict__ maskr) {
    const int b = blockIdx.y, ch = blockIdx.x;
    const int tid = threadIdx.x;
    __shared__ float w_s[CHUNK];
    __shared__ int s_idx, s_nv;
    if (tid == 0) {
        s_idx = g_index[b];
        int nv = decode_mask(maskr, b) - ch*CHUNK;
        s_nv = nv < 0 ? 0 : (nv > CHUNK ? CHUNK : nv);
    }
    __syncthreads();
    const int nv = s_nv;
    float* gp = g_part + ((size_t)b*NCHUNK + ch)*DD;
    if (nv == 0) {
        ((float2*)gp)[tid] = make_float2(0.f, 0.f);
        return;
    }
    const int idx = s_idx;
    const int rowbase = b*NN + ch*CHUNK;
    if (tid < CHUNK) w_s[tid] = (tid < nv) ? g_sw[(size_t)(rowbase + tid)*CC + idx] : 0.f;
    __syncthreads();
    float ax = 0.f, ay = 0.f;
    const __half2* xb = (const __half2*)(g_xh + (size_t)rowbase*DD) + tid;
    int r = 0;
    for (; r + 16 <= nv; r += 16) {
        __half2 vv[16];
        #pragma unroll
        for (int u = 0; u < 16; u++) vv[u] = xb[(size_t)(r+u)*256];
        #pragma unroll
        for (int u = 0; u < 16; u++) {
            float2 f = __half22float2(vv[u]);
            float w = w_s[r+u];
            ax = fmaf(f.x, w, ax);
            ay = fmaf(f.y, w, ay);
        }
    }
    for (; r < nv; r++) {
        float2 f = __half22float2(xb[(size_t)r*256]);
        float w = w_s[r];
        ax = fmaf(f.x, w, ax);
        ay = fmaf(f.y, w, ay);
    }
    ((float2*)gp)[tid] = make_float2(ax, ay);
}

// 256 blocks x 256 threads: 64 outputs/block, 4-way chunk split + smem combine
__global__ void feat_reduce_kernel(float* __restrict__ out) {
    __shared__ float sm[256];
    const int o = threadIdx.x & 63, s = threadIdx.x >> 6;
    const int gidx = blockIdx.x*64 + o;     // 0..16383
    const int b = gidx >> 9, d = gidx & 511;
    const float* gp = g_part + ((size_t)b*NCHUNK + s*8)*DD + d;
    float sum = 0.f;
    #pragma unroll
    for (int i = 0; i < 8; i++) sum += gp[i*DD];
    sm[threadIdx.x] = sum;
    __syncthreads();
    if (s == 0) out[gidx] = sm[o] + sm[64 + o] + sm[128 + o] + sm[192 + o];
}

extern "C" void kernel_launch(void* const* d_in, const int* in_sizes, int n_in,
                              void* d_out, int out_size) {
    const float* x       = (const float*)d_in[0];
    const int*   mask    = (const int*)d_in[1];
    const float* anchors = (const float*)d_in[2];
    float* out = (float*)d_out;

    const size_t smem = (size_t)(CC*PB + MT*PB)                // int8 tiles
                      + (size_t)(2*MT*DP)*sizeof(int)          // dots
                      + (size_t)(2*CC + 2*MT)*sizeof(float)
                      + BB*sizeof(int);                        // ~68.5 KB
    cudaFuncSetAttribute(main_kernel, cudaFuncAttributeMaxDynamicSharedMemorySize, (int)smem);

    main_kernel<<<152, 512, smem>>>(x, mask, anchors);
    index_kernel<<<BB, CC>>>();
    dim3 g(NCHUNK, BB);
    feat_part_kernel<<<g, 256>>>(mask);
    feat_reduce_kernel<<<256, 256>>>(out);
}

// round 15
// speedup vs baseline: 1.1983x; 1.1983x over previous
#include <cuda_runtime.h>
#include <cuda_fp16.h>
#include <math.h>
#include <stdint.h>

// Problem constants
#define BB 32
#define NN 4096
#define DD 512
#define CC 64
#define RTOT (BB*NN)          // 131072 rows
#define MT 32                 // rows per GEMM tile
#define NTILES (RTOT/MT)      // 4096
#define XPH 520               // x_s pitch in halves: 260 words ≡ 4 (mod 32) -> conflict-free
#define APH 520               // anchor pitch in halves
#define CHUNK 128             // rows per feature chunk
#define NCHUNK (NN/CHUNK)     // 32

// Device scratch (allocation-free rule: __device__ globals)
__device__ float  g_sw[(size_t)RTOT*CC];          // score*invnorm*valid, 32 MiB
__device__ __half g_xh[(size_t)RTOT*DD];          // x in fp16 (written by main), 128 MiB
__device__ int    g_counts[BB*CC];
__device__ int    g_index[BB];
__device__ float  g_part[(size_t)BB*NCHUNK*DD];   // 2 MiB

// mask may be int64 (jax x64) or int32. Values in [1,4096]: if int64 LE,
// word 1 (high half of elem 0) is 0.
__device__ __forceinline__ int decode_mask(const int* mr, int b) {
    return (mr[1] == 0) ? mr[2*b] : mr[b];
}

// fp16-accumulate mma: C/D packed as 2x half2 registers
__device__ __forceinline__ void mma_f16acc(unsigned& c0, unsigned& c1,
                                           unsigned a0, unsigned a1, unsigned a2, unsigned a3,
                                           unsigned b0, unsigned b1) {
    asm volatile("mma.sync.aligned.m16n8k16.row.col.f16.f16.f16.f16 "
                 "{%0,%1}, {%2,%3,%4,%5}, {%6,%7}, {%0,%1};"
                 : "+r"(c0), "+r"(c1)
                 : "r"(a0), "r"(a1), "r"(a2), "r"(a3), "r"(b0), "r"(b1));
}

__global__ __launch_bounds__(512, 1)
void main_kernel(const float* __restrict__ x, const int* __restrict__ maskr,
                 const float* __restrict__ anchors) {
    extern __shared__ char smem[];
    __half*   a_h    = (__half*)smem;                    // [CC][APH] anchors fp16
    __half*   x_h    = a_h + CC*APH;                     // [MT][XPH] x tile fp16
    float*    dots_s = (float*)(x_h + MT*XPH);           // [2][MT][CC] k-half partials
    float*    anorm_s= dots_s + 2*MT*CC;                 // [CC]
    float*    norm_s = anorm_s + CC;                     // [MT]
    int*      mask_s = (int*)(norm_s + MT);              // [BB]
    int*      pref_s = mask_s + BB;                      // [BB+1] valid-tile prefix sums

    const int tid  = threadIdx.x;
    const int lane = tid & 31, warp = tid >> 5;           // 16 warps

    // ---- anchors -> smem fp16, [c][k] pitch APH ----
    for (int i = tid; i < CC*DD; i += 512) {
        int c = i >> 9, k = i & (DD-1);
        a_h[c*APH + k] = __float2half_rn(anchors[i]);
    }
    if (tid < BB) mask_s[tid] = decode_mask(maskr, tid);
    if (tid < CC) {
        float s = 0.f;
        const float* ar = anchors + (size_t)tid*DD;
        #pragma unroll 8
        for (int k = 0; k < DD; k++) { float q = ar[k]; s = fmaf(q, q, s); }
        anorm_s[tid] = s;
    }
    __syncthreads();
    if (tid == 0) {
        int acc = 0;
        #pragma unroll
        for (int i = 0; i < BB; i++) {
            pref_s[i] = acc;
            acc += (mask_s[i] + MT - 1) >> 5;    // valid tiles in batch i
        }
        pref_s[BB] = acc;
    }
    __syncthreads();
    const int V = pref_s[BB];                    // total valid tiles (balanced work units)

    // warp decomposition: mslice (2) x nslice (4) x khalf (2)
    const int gid = lane >> 2, tig = lane & 3;
    const int mbase = (warp & 1) * 16;
    const int nb0   = ((warp >> 1) & 3) * 16;
    const int kh    = warp >> 3;                 // 0/1: k offset kh*256

    // load mapping: thread -> one row, 8 float4 slots
    const int lrow  = tid >> 4;                  // 0..31
    const int lslot = tid & 15;

    // map compact valid-index -> (batch, rowbase) via binary search over pref_s
    auto map_vi = [&](int vi, int& bout) -> int {
        int lo = 0, hi = BB - 1;
        #pragma unroll
        for (int s = 0; s < 5; s++) {
            int mid = (lo + hi + 1) >> 1;
            if (pref_s[mid] <= vi) lo = mid; else hi = mid - 1;
        }
        bout = lo;
        return lo*NN + (vi - pref_s[lo])*MT;
    };

    // ---- prefetch first work unit ----
    int vi = blockIdx.x;
    int b = 0, rowbase = 0;
    float4 v[8];
    if (vi < V) {
        rowbase = map_vi(vi, b);
        const float4* xg = (const float4*)(x + (size_t)rowbase*DD) + lrow*128 + lslot;
        #pragma unroll
        for (int j = 0; j < 8; j++) v[j] = xg[16*j];
    }

    while (vi < V) {
        // ---- store tile to smem (fp16) + mirror to g_xh + row norm ----
        float ns = 0.f;
        {
            uint2* xhrow = (uint2*)(g_xh + (size_t)(rowbase + lrow)*DD);
            #pragma unroll
            for (int j = 0; j < 8; j++) {
                float4 q = v[j];
                __half2 h01 = __floats2half2_rn(q.x, q.y);
                __half2 h23 = __floats2half2_rn(q.z, q.w);
                uint2 st;
                st.x = *(unsigned*)&h01;
                st.y = *(unsigned*)&h23;
                *(uint2*)((char*)x_h + lrow*(XPH*2) + (lslot + 16*j)*8) = st;
                xhrow[lslot + 16*j] = st;
                ns = fmaf(q.x,q.x, fmaf(q.y,q.y, fmaf(q.z,q.z, fmaf(q.w,q.w, ns))));
            }
        }
        #pragma unroll
        for (int o = 8; o; o >>= 1) ns += __shfl_xor_sync(0xffffffffu, ns, o);
        if ((lane & 15) == 0) norm_s[lrow] = ns;
        __syncthreads();

        // ---- prefetch next work unit (overlaps with mma) ----
        const int nvi = vi + gridDim.x;
        int nb = 0, nrowbase = 0;
        if (nvi < V) {
            nrowbase = map_vi(nvi, nb);
            const float4* xg = (const float4*)(x + (size_t)nrowbase*DD) + lrow*128 + lslot;
            #pragma unroll
            for (int j = 0; j < 8; j++) v[j] = xg[16*j];
        }

        // ---- fp16 mma, fp16 accumulate in chains of 4, fp32 promotion ----
        float d00=0,d01=0,d02=0,d03=0, d10=0,d11=0,d12=0,d13=0;
        const __half* xa  = x_h + (mbase + gid)*XPH + kh*256 + 2*tig;
        const __half* b0p = a_h + (nb0 + gid)*APH     + kh*256 + 2*tig;
        const __half* b1p = a_h + (nb0 + gid + 8)*APH + kh*256 + 2*tig;
        #pragma unroll
        for (int g = 0; g < 4; g++) {
            unsigned e00=0, e01=0, e10=0, e11=0;
            #pragma unroll
            for (int s = 0; s < 4; s++) {
                const int k0 = (g*4 + s)*16;
                unsigned a0 = *(const unsigned*)(xa + k0);
                unsigned a1 = *(const unsigned*)(xa + 8*XPH + k0);
                unsigned a2 = *(const unsigned*)(xa + k0 + 8);
                unsigned a3 = *(const unsigned*)(xa + 8*XPH + k0 + 8);
                unsigned b00 = *(const unsigned*)(b0p + k0);
                unsigned b01 = *(const unsigned*)(b0p + k0 + 8);
                unsigned b10 = *(const unsigned*)(b1p + k0);
                unsigned b11 = *(const unsigned*)(b1p + k0 + 8);
                mma_f16acc(e00, e01, a0,a1,a2,a3, b00,b01);
                mma_f16acc(e10, e11, a0,a1,a2,a3, b10,b11);
            }
            {
                float2 f;
                f = __half22float2(*(__half2*)&e00); d00 += f.x; d01 += f.y;
                f = __half22float2(*(__half2*)&e01); d02 += f.x; d03 += f.y;
                f = __half22float2(*(__half2*)&e10); d10 += f.x; d11 += f.y;
                f = __half22float2(*(__half2*)&e11); d12 += f.x; d13 += f.y;
            }
        }
        {
            float* dh = dots_s + kh*MT*CC;
            const int r0 = mbase + gid, r1 = r0 + 8, cb = 2*tig;
            dh[r0*CC + nb0 + cb]     = d00;
            dh[r0*CC + nb0 + cb + 1] = d01;
            dh[r1*CC + nb0 + cb]     = d02;
            dh[r1*CC + nb0 + cb + 1] = d03;
            dh[r0*CC + nb0 + 8 + cb]     = d10;
            dh[r0*CC + nb0 + 8 + cb + 1] = d11;
            dh[r1*CC + nb0 + 8 + cb]     = d12;
            dh[r1*CC + nb0 + 8 + cb + 1] = d13;
        }
        __syncthreads();

        // ---- epilogue: 2 rows per warp; softmax without max-shift ----
        // (invd <= ~0.09 always since ||anchor|| >= ~12, ||xn|| = 1 -> no overflow)
        #pragma unroll
        for (int u = 0; u < 2; u++) {
            const int m = warp*2 + u;
            const int row = rowbase + m;
            const int n = row & (NN-1);
            const bool valid = n < mask_s[b];
            const float n2  = norm_s[m];
            const float inv = 1.f / fmaxf(sqrtf(n2), 1e-12f);
            const float sxn2 = n2 * inv * inv;
            const int cA = lane, cB = lane + 32;
            const float dA = dots_s[m*CC + cA] + dots_s[MT*CC + m*CC + cA];
            const float dB = dots_s[m*CC + cB] + dots_s[MT*CC + m*CC + cB];
            const float sqA = sxn2 + anorm_s[cA] - 2.f*dA*inv;
            const float sqB = sxn2 + anorm_s[cB] - 2.f*dB*inv;
            const float idA = rsqrtf(fmaxf(sqA, 1e-30f));
            const float idB = rsqrtf(fmaxf(sqB, 1e-30f));
            const float eA = __expf(idA), eB = __expf(idB);
            float ss = eA + eB;
            #pragma unroll
            for (int o = 16; o; o >>= 1) ss += __shfl_xor_sync(0xffffffffu, ss, o);
            const float rs = 1.f / ss;
            const size_t base = (size_t)row * CC;
            g_sw[base + cA] = valid ? eA*rs*inv : 0.f;
            g_sw[base + cB] = valid ? eB*rs*inv : 0.f;
            float bv; int bi;
            if (idB > idA) { bv = idB; bi = cB; } else { bv = idA; bi = cA; }
            #pragma unroll
            for (int o = 16; o; o >>= 1) {
                float ov = __shfl_xor_sync(0xffffffffu, bv, o);
                int   oi = __shfl_xor_sync(0xffffffffu, bi, o);
                if (ov > bv || (ov == bv && oi < bi)) { bv = ov; bi = oi; }
            }
            if (lane == 0 && valid) atomicAdd(&g_counts[b*CC + bi], 1);
        }
        __syncthreads();
        vi = nvi; b = nb; rowbase = nrowbase;
    }
}

// argmax of counts per batch; also resets counts for the next graph replay
__global__ void index_kernel() {
    __shared__ int sv[CC], si[CC];
    const int b = blockIdx.x, c = threadIdx.x;
    sv[c] = g_counts[b*CC + c]; si[c] = c;
    g_counts[b*CC + c] = 0;
    __syncthreads();
    for (int o = 32; o; o >>= 1) {
        if (c < o) {
            if (sv[c+o] > sv[c] || (sv[c+o] == sv[c] && si[c+o] < si[c])) {
                sv[c] = sv[c+o]; si[c] = si[c+o];
            }
        }
        __syncthreads();
    }
    if (c == 0) g_index[b] = si[0];
}

// reads fp16 x copy (half traffic); thread tid covers d = {2*tid, 2*tid+1}
__global__ __launch_bounds__(256)
void feat_part_kernel(const int* __restrict__ maskr) {
    const int b = blockIdx.y, ch = blockIdx.x;
    const int tid = threadIdx.x;
    __shared__ float w_s[CHUNK];
    __shared__ int s_idx, s_nv;
    if (tid == 0) {
        s_idx = g_index[b];
        int nv = decode_mask(maskr, b) - ch*CHUNK;
        s_nv = nv < 0 ? 0 : (nv > CHUNK ? CHUNK : nv);
    }
    __syncthreads();
    const int nv = s_nv;
    float* gp = g_part + ((size_t)b*NCHUNK + ch)*DD;
    if (nv == 0) {
        ((float2*)gp)[tid] = make_float2(0.f, 0.f);
        return;
    }
    const int idx = s_idx;
    const int rowbase = b*NN + ch*CHUNK;
    if (tid < CHUNK) w_s[tid] = (tid < nv) ? g_sw[(size_t)(rowbase + tid)*CC + idx] : 0.f;
    __syncthreads();
    float ax = 0.f, ay = 0.f;
    const __half2* xb = (const __half2*)(g_xh + (size_t)rowbase*DD) + tid;
    int r = 0;
    for (; r + 16 <= nv; r += 16) {
        __half2 vv[16];
        #pragma unroll
        for (int u = 0; u < 16; u++) vv[u] = xb[(size_t)(r+u)*256];
        #pragma unroll
        for (int u = 0; u < 16; u++) {
            float2 f = __half22float2(vv[u]);
            float w = w_s[r+u];
            ax = fmaf(f.x, w, ax);
            ay = fmaf(f.y, w, ay);
        }
    }
    for (; r < nv; r++) {
        float2 f = __half22float2(xb[(size_t)r*256]);
        float w = w_s[r];
        ax = fmaf(f.x, w, ax);
        ay = fmaf(f.y, w, ay);
    }
    ((float2*)gp)[tid] = make_float2(ax, ay);
}

// 256 blocks x 256 threads: 64 outputs/block, 4-way chunk split + smem combine
__global__ void feat_reduce_kernel(float* __restrict__ out) {
    __shared__ float sm[256];
    const int o = threadIdx.x & 63, s = threadIdx.x >> 6;
    const int gidx = blockIdx.x*64 + o;     // 0..16383
    const int b = gidx >> 9, d = gidx & 511;
    const float* gp = g_part + ((size_t)b*NCHUNK + s*8)*DD + d;
    float sum = 0.f;
    #pragma unroll
    for (int i = 0; i < 8; i++) sum += gp[i*DD];
    sm[threadIdx.x] = sum;
    __syncthreads();
    if (s == 0) out[gidx] = sm[o] + sm[64 + o] + sm[128 + o] + sm[192 + o];
}

extern "C" void kernel_launch(void* const* d_in, const int* in_sizes, int n_in,
                              void* d_out, int out_size) {
    const float* x       = (const float*)d_in[0];
    const int*   mask    = (const int*)d_in[1];
    const float* anchors = (const float*)d_in[2];
    float* out = (float*)d_out;

    const size_t smem = (size_t)(CC*APH + MT*XPH)*sizeof(__half)
                      + (size_t)(2*MT*CC + CC + MT)*sizeof(float)
                      + (2*BB + 1)*sizeof(int);   // ~117 KB
    cudaFuncSetAttribute(main_kernel, cudaFuncAttributeMaxDynamicSharedMemorySize, (int)smem);

    main_kernel<<<152, 512, smem>>>(x, mask, anchors);
    index_kernel<<<BB, CC>>>();
    dim3 g(NCHUNK, BB);
    feat_part_kernel<<<g, 256>>>(mask);
    feat_reduce_kernel<<<256, 256>>>(out);
}